// round 1
// baseline (speedup 1.0000x reference)
#include <cuda_runtime.h>
#include <math.h>

#define L_SEQ  4096
#define DMODEL 1024
#define NHEADS 16
#define HDIM   64

// Scratch (allocation-free rule: __device__ globals)
__device__ float g_q[NHEADS * L_SEQ * HDIM];
__device__ float g_k[NHEADS * L_SEQ * HDIM];
__device__ float g_v[NHEADS * L_SEQ * HDIM];
__device__ float g_attn[L_SEQ * DMODEL];

// ---------------------------------------------------------------------------
// SGEMM: C = A(MxK) * B(KxN), all row-major fp32.
// MODE 0: C[row*N + col]
// MODE 1: head-major: C[((col>>6)*M + row)*64 + (col&63)]  (BN=64 => one head/block)
// ---------------------------------------------------------------------------
#define BM 128
#define BN 64
#define BK 16
#define TM 8
#define TN 4

template <int MODE>
__global__ __launch_bounds__(256) void sgemm(const float* __restrict__ A,
                                             const float* __restrict__ B,
                                             float* __restrict__ C,
                                             int M, int N, int K) {
    __shared__ float As[BK * 132];  // [k][m], padded stride 132 (float4-aligned)
    __shared__ float Bs[BK * BN];   // [k][n]

    const int tid  = threadIdx.x;
    const int tx   = tid & 15;   // 16 col-groups of TN
    const int ty   = tid >> 4;   // 16 row-groups of TM
    const int row0 = blockIdx.y * BM;
    const int col0 = blockIdx.x * BN;

    float acc[TM][TN];
#pragma unroll
    for (int i = 0; i < TM; i++)
#pragma unroll
        for (int j = 0; j < TN; j++) acc[i][j] = 0.f;

    for (int k0 = 0; k0 < K; k0 += BK) {
        // Load A tile (128x16) as 512 float4s, 2 per thread; store transposed.
#pragma unroll
        for (int q = tid; q < 512; q += 256) {
            int r   = q >> 2;
            int kk4 = q & 3;
            float4 av = *(const float4*)&A[(size_t)(row0 + r) * K + k0 + kk4 * 4];
            As[(kk4 * 4 + 0) * 132 + r] = av.x;
            As[(kk4 * 4 + 1) * 132 + r] = av.y;
            As[(kk4 * 4 + 2) * 132 + r] = av.z;
            As[(kk4 * 4 + 3) * 132 + r] = av.w;
        }
        // Load B tile (16x64) as 256 float4s, 1 per thread.
        {
            int kk = tid >> 4;
            int n4 = tid & 15;
            *(float4*)&Bs[kk * BN + n4 * 4] =
                *(const float4*)&B[(size_t)(k0 + kk) * N + col0 + n4 * 4];
        }
        __syncthreads();

#pragma unroll
        for (int k = 0; k < BK; k++) {
            float4 a0 = *(float4*)&As[k * 132 + ty * TM];
            float4 a1 = *(float4*)&As[k * 132 + ty * TM + 4];
            float4 b0 = *(float4*)&Bs[k * BN + tx * TN];
            float a[TM] = {a0.x, a0.y, a0.z, a0.w, a1.x, a1.y, a1.z, a1.w};
            float b[TN] = {b0.x, b0.y, b0.z, b0.w};
#pragma unroll
            for (int i = 0; i < TM; i++)
#pragma unroll
                for (int j = 0; j < TN; j++)
                    acc[i][j] = fmaf(a[i], b[j], acc[i][j]);
        }
        __syncthreads();
    }

#pragma unroll
    for (int i = 0; i < TM; i++) {
        int row = row0 + ty * TM + i;
        float4 v = make_float4(acc[i][0], acc[i][1], acc[i][2], acc[i][3]);
        if (MODE == 0) {
            *(float4*)&C[(size_t)row * N + col0 + tx * TN] = v;
        } else {
            int head = col0 >> 6;
            *(float4*)&C[((size_t)head * M + row) * 64 + tx * TN] = v;
        }
    }
}

// ---------------------------------------------------------------------------
// Flash attention with ALiBi + causal mask. One block = (head h, 64 q-rows).
// 64 threads; thread t owns query row i0+t. Q and O live in registers.
// Scores staged per-tile in smem (own row only) for a clean 2-pass softmax.
// ---------------------------------------------------------------------------
__global__ __launch_bounds__(64) void attn_kernel() {
    __shared__ float Qs[64 * 64];  // Q staging -> per-thread score rows -> O staging
    __shared__ float Ks[64 * 64];
    __shared__ float Vs[64 * 64];

    const int h  = blockIdx.y;
    const int bx = blockIdx.x;
    const int i0 = bx * 64;
    const int t  = threadIdx.x;
    const int i  = i0 + t;

    // Coalesced Q tile load, then copy own row to registers.
    const float* qp = g_q + ((size_t)h * L_SEQ + i0) * HDIM;
    for (int r = 0; r < 64; r++) Qs[r * 64 + t] = qp[r * 64 + t];
    __syncthreads();
    float qreg[64];
#pragma unroll
    for (int d = 0; d < 64; d++) qreg[d] = Qs[t * 64 + d];

    float m = -INFINITY, lsum = 0.f;
    float o[64];
#pragma unroll
    for (int d = 0; d < 64; d++) o[d] = 0.f;
    const float slope = exp2f(-0.5f * (float)(h + 1));

    for (int kb = 0; kb <= bx; kb++) {
        const int j0 = kb * 64;
        const float* kp = g_k + ((size_t)h * L_SEQ + j0) * HDIM;
        const float* vp = g_v + ((size_t)h * L_SEQ + j0) * HDIM;
        __syncthreads();  // prior pass-2 reads of Vs done
        for (int r = 0; r < 64; r++) {
            Ks[r * 64 + t] = kp[r * 64 + t];
            Vs[r * 64 + t] = vp[r * 64 + t];
        }
        __syncthreads();

        // Pass 1: scores (4 accumulators to break the FMA latency chain).
        float mt = m;
        if (kb < bx) {  // full tile: no causal check needed
#pragma unroll 2
            for (int j = 0; j < 64; j++) {
                float c0 = 0.f, c1 = 0.f, c2 = 0.f, c3 = 0.f;
#pragma unroll
                for (int d = 0; d < 64; d += 4) {
                    c0 = fmaf(qreg[d + 0], Ks[j * 64 + d + 0], c0);
                    c1 = fmaf(qreg[d + 1], Ks[j * 64 + d + 1], c1);
                    c2 = fmaf(qreg[d + 2], Ks[j * 64 + d + 2], c2);
                    c3 = fmaf(qreg[d + 3], Ks[j * 64 + d + 3], c3);
                }
                float s = (c0 + c1) + (c2 + c3);
                s = s * 0.125f - slope * (float)(i - (j0 + j));
                Qs[t * 64 + j] = s;
                mt = fmaxf(mt, s);
            }
        } else {  // diagonal tile: causal mask
#pragma unroll 2
            for (int j = 0; j < 64; j++) {
                float s = -INFINITY;
                if (j0 + j <= i) {
                    float c0 = 0.f, c1 = 0.f, c2 = 0.f, c3 = 0.f;
#pragma unroll
                    for (int d = 0; d < 64; d += 4) {
                        c0 = fmaf(qreg[d + 0], Ks[j * 64 + d + 0], c0);
                        c1 = fmaf(qreg[d + 1], Ks[j * 64 + d + 1], c1);
                        c2 = fmaf(qreg[d + 2], Ks[j * 64 + d + 2], c2);
                        c3 = fmaf(qreg[d + 3], Ks[j * 64 + d + 3], c3);
                    }
                    s = (c0 + c1) + (c2 + c3);
                    s = s * 0.125f - slope * (float)(i - (j0 + j));
                }
                Qs[t * 64 + j] = s;
                mt = fmaxf(mt, s);
            }
        }

        // Rescale running state.
        float corr = __expf(m - mt);  // m=-inf -> 0 (o,lsum already 0)
        m = mt;
        lsum *= corr;
#pragma unroll
        for (int d = 0; d < 64; d++) o[d] *= corr;

        // Pass 2: probabilities + PV accumulate (64-wide ILP across o[]).
#pragma unroll 2
        for (int j = 0; j < 64; j++) {
            float p = __expf(Qs[t * 64 + j] - m);  // -inf scores -> 0
            lsum += p;
#pragma unroll
            for (int d = 0; d < 64; d++)
                o[d] = fmaf(p, Vs[j * 64 + d], o[d]);
        }
    }

    // Normalize, stage through smem, coalesced write into [L, DMODEL] layout.
    const float inv = 1.0f / lsum;
    __syncthreads();
#pragma unroll
    for (int d = 0; d < 64; d++) Qs[t * 64 + d] = o[d] * inv;
    __syncthreads();
    float* op = g_attn + (size_t)i0 * DMODEL + h * HDIM;
    for (int r = 0; r < 64; r++) op[r * DMODEL + t] = Qs[r * 64 + t];
}

// ---------------------------------------------------------------------------
extern "C" void kernel_launch(void* const* d_in, const int* in_sizes, int n_in,
                              void* d_out, int out_size) {
    const float* x  = (const float*)d_in[0];
    const float* qw = (const float*)d_in[1];
    const float* kw = (const float*)d_in[2];
    const float* vw = (const float*)d_in[3];
    const float* ow = (const float*)d_in[4];
    float* out = (float*)d_out;

    float *pq, *pk, *pv, *pa;
    cudaGetSymbolAddress((void**)&pq, g_q);
    cudaGetSymbolAddress((void**)&pk, g_k);
    cudaGetSymbolAddress((void**)&pv, g_v);
    cudaGetSymbolAddress((void**)&pa, g_attn);

    dim3 gp(DMODEL / BN, L_SEQ / BM);
    sgemm<1><<<gp, 256>>>(x, qw, pq, L_SEQ, DMODEL, DMODEL);
    sgemm<1><<<gp, 256>>>(x, kw, pk, L_SEQ, DMODEL, DMODEL);
    sgemm<1><<<gp, 256>>>(x, vw, pv, L_SEQ, DMODEL, DMODEL);

    dim3 ga(L_SEQ / 64, NHEADS);
    attn_kernel<<<ga, 64>>>();

    sgemm<0><<<gp, 256>>>(pa, ow, out, L_SEQ, DMODEL, DMODEL);
}

// round 2
// speedup vs baseline: 1.2349x; 1.2349x over previous
#include <cuda_runtime.h>
#include <math.h>

#define L_SEQ  4096
#define DMODEL 1024
#define NHEADS 16
#define HDIM   64

// Scratch (allocation-free rule: __device__ globals)
__device__ float g_q[NHEADS * L_SEQ * HDIM];
__device__ float g_k[NHEADS * L_SEQ * HDIM];
__device__ float g_v[NHEADS * L_SEQ * HDIM];
__device__ float g_attn[L_SEQ * DMODEL];

// ---------------------------------------------------------------------------
// SGEMM: C = A(MxK) * B(KxN), row-major fp32. 128x128x16 tile, 256 threads,
// 8x8 per thread (split 4+4 for conflict-free LDS.128), register
// double-buffered global loads.
// MODE 0: C[row*N + col]
// MODE 1: head-major: C[((col>>6)*M + row)*64 + (col&63)]
// ---------------------------------------------------------------------------
#define BM 128
#define BN 128
#define BK 16

template <int MODE>
__global__ __launch_bounds__(256, 2) void sgemm(const float* __restrict__ A,
                                                const float* __restrict__ B,
                                                float* __restrict__ C,
                                                int M, int N, int K) {
    __shared__ float As[BK * 132];  // [k][m], padded
    __shared__ float Bs[BK * BN];   // [k][n]

    const int tid  = threadIdx.x;
    const int tx   = tid & 15;
    const int ty   = tid >> 4;
    const int row0 = blockIdx.y * BM;
    const int col0 = blockIdx.x * BN;

    // A-load slots: s = tid + i*256 -> row = s>>2, kq = s&3 (float4 along k)
    const int a_row0 = tid >> 2;
    const int a_kq   = tid & 3;
    // B-load slots: k = (tid>>5) + i*8, n4 = tid&31 (float4 along n)
    const int b_k0 = tid >> 5;
    const int b_n4 = tid & 31;

    float acc[8][8];
#pragma unroll
    for (int i = 0; i < 8; i++)
#pragma unroll
        for (int j = 0; j < 8; j++) acc[i][j] = 0.f;

    float4 a_ld[2], b_ld[2];

    // Prologue: load tile 0
#pragma unroll
    for (int i = 0; i < 2; i++) {
        a_ld[i] = *(const float4*)&A[(size_t)(row0 + a_row0 + i * 64) * K + a_kq * 4];
        b_ld[i] = *(const float4*)&B[(size_t)(b_k0 + i * 8) * N + col0 + b_n4 * 4];
    }
#pragma unroll
    for (int i = 0; i < 2; i++) {
        int r = a_row0 + i * 64;
        As[(a_kq * 4 + 0) * 132 + r] = a_ld[i].x;
        As[(a_kq * 4 + 1) * 132 + r] = a_ld[i].y;
        As[(a_kq * 4 + 2) * 132 + r] = a_ld[i].z;
        As[(a_kq * 4 + 3) * 132 + r] = a_ld[i].w;
        *(float4*)&Bs[(b_k0 + i * 8) * BN + b_n4 * 4] = b_ld[i];
    }
    __syncthreads();

    for (int k0 = 0; k0 < K; k0 += BK) {
        const bool has_next = (k0 + BK) < K;
        if (has_next) {
#pragma unroll
            for (int i = 0; i < 2; i++) {
                a_ld[i] = *(const float4*)&A[(size_t)(row0 + a_row0 + i * 64) * K + k0 + BK + a_kq * 4];
                b_ld[i] = *(const float4*)&B[(size_t)(k0 + BK + b_k0 + i * 8) * N + col0 + b_n4 * 4];
            }
        }

#pragma unroll
        for (int k = 0; k < BK; k++) {
            float a[8], b[8];
            *(float4*)&a[0] = *(float4*)&As[k * 132 + ty * 4];
            *(float4*)&a[4] = *(float4*)&As[k * 132 + 64 + ty * 4];
            *(float4*)&b[0] = *(float4*)&Bs[k * BN + tx * 4];
            *(float4*)&b[4] = *(float4*)&Bs[k * BN + 64 + tx * 4];
#pragma unroll
            for (int i = 0; i < 8; i++)
#pragma unroll
                for (int j = 0; j < 8; j++)
                    acc[i][j] = fmaf(a[i], b[j], acc[i][j]);
        }
        __syncthreads();
        if (has_next) {
#pragma unroll
            for (int i = 0; i < 2; i++) {
                int r = a_row0 + i * 64;
                As[(a_kq * 4 + 0) * 132 + r] = a_ld[i].x;
                As[(a_kq * 4 + 1) * 132 + r] = a_ld[i].y;
                As[(a_kq * 4 + 2) * 132 + r] = a_ld[i].z;
                As[(a_kq * 4 + 3) * 132 + r] = a_ld[i].w;
                *(float4*)&Bs[(b_k0 + i * 8) * BN + b_n4 * 4] = b_ld[i];
            }
            __syncthreads();
        }
    }

    // Epilogue
#pragma unroll
    for (int ci = 0; ci < 2; ci++) {
#pragma unroll
        for (int r = 0; r < 4; r++) {
            int row = row0 + ci * 64 + ty * 4 + r;
#pragma unroll
            for (int cj = 0; cj < 2; cj++) {
                int col = col0 + cj * 64 + tx * 4;
                float4 v = make_float4(acc[ci * 4 + r][cj * 4 + 0],
                                       acc[ci * 4 + r][cj * 4 + 1],
                                       acc[ci * 4 + r][cj * 4 + 2],
                                       acc[ci * 4 + r][cj * 4 + 3]);
                if (MODE == 0) {
                    *(float4*)&C[(size_t)row * N + col] = v;
                } else {
                    int head = col >> 6;
                    *(float4*)&C[((size_t)head * M + row) * 64 + (col & 63)] = v;
                }
            }
        }
    }
}

// ---------------------------------------------------------------------------
// Flash attention with ALiBi + causal mask.
// Block = (head h, 64 q-rows). 128 threads: t = row*2 + half.
// Thread owns q-row (t>>1), d-half (t&1): qreg[32], o[32] in registers.
// All smem traffic is float4 / broadcast; score buffer transposed [j][row].
// ---------------------------------------------------------------------------
__global__ __launch_bounds__(128, 4) void attn_kernel() {
    __shared__ float Ks[64 * 64];
    __shared__ float Vs[64 * 64];
    __shared__ float Sc[64 * 64];  // [j][row]

    const int h  = blockIdx.y;
    const int bx = blockIdx.x;
    const int i0 = bx * 64;
    const int t  = threadIdx.x;
    const int hf = t & 1;
    const int row = t >> 1;
    const int i  = i0 + row;
    const float slope = exp2f(-0.5f * (float)(h + 1));

    // Load own q row-half, prescaled by 1/sqrt(hd)=0.125
    float qreg[32];
    {
        const float* qp = g_q + ((size_t)h * L_SEQ + i) * HDIM + hf * 32;
#pragma unroll
        for (int d = 0; d < 32; d += 4) {
            float4 v = *(const float4*)&qp[d];
            qreg[d + 0] = v.x * 0.125f;
            qreg[d + 1] = v.y * 0.125f;
            qreg[d + 2] = v.z * 0.125f;
            qreg[d + 3] = v.w * 0.125f;
        }
    }

    float m = -INFINITY, lsum = 0.f;
    float o[32];
#pragma unroll
    for (int d = 0; d < 32; d++) o[d] = 0.f;

    for (int kb = 0; kb <= bx; kb++) {
        const int j0 = kb * 64;
        const float* kp = g_k + ((size_t)h * L_SEQ + j0) * HDIM;
        const float* vp = g_v + ((size_t)h * L_SEQ + j0) * HDIM;
        __syncthreads();  // prior pass-2 reads of Ks/Vs done
#pragma unroll
        for (int idx = t; idx < 1024; idx += 128) {
            *(float4*)&Ks[idx * 4] = *(const float4*)&kp[idx * 4];
            *(float4*)&Vs[idx * 4] = *(const float4*)&vp[idx * 4];
        }
        __syncthreads();

        const bool diag = (kb == bx);
        float mt = m;
#pragma unroll 2
        for (int j = 0; j < 64; j++) {
            const float* kr = &Ks[j * 64 + hf * 32];
            float c0 = 0.f, c1 = 0.f, c2 = 0.f, c3 = 0.f;
#pragma unroll
            for (int d = 0; d < 32; d += 4) {
                float4 kv = *(const float4*)&kr[d];
                c0 = fmaf(qreg[d + 0], kv.x, c0);
                c1 = fmaf(qreg[d + 1], kv.y, c1);
                c2 = fmaf(qreg[d + 2], kv.z, c2);
                c3 = fmaf(qreg[d + 3], kv.w, c3);
            }
            float part = (c0 + c1) + (c2 + c3);
            float s = part + __shfl_xor_sync(0xffffffffu, part, 1);
            s -= slope * (float)(i - (j0 + j));
            if (diag && j > row) s = -INFINITY;
            if (hf == 0) Sc[j * 64 + row] = s;
            mt = fmaxf(mt, s);
        }

        // Rescale running state
        float corr = __expf(m - mt);  // m=-inf -> 0 (o,lsum already 0)
        m = mt;
        lsum *= corr;
#pragma unroll
        for (int d = 0; d < 32; d++) o[d] *= corr;
        __syncwarp();  // Sc visible within warp (writer is lane-partner)

#pragma unroll 2
        for (int j = 0; j < 64; j++) {
            float p = __expf(Sc[j * 64 + row] - m);  // -inf -> 0
            lsum += p;
            const float* vr = &Vs[j * 64 + hf * 32];
#pragma unroll
            for (int d = 0; d < 32; d += 4) {
                float4 vv = *(const float4*)&vr[d];
                o[d + 0] = fmaf(p, vv.x, o[d + 0]);
                o[d + 1] = fmaf(p, vv.y, o[d + 1]);
                o[d + 2] = fmaf(p, vv.z, o[d + 2]);
                o[d + 3] = fmaf(p, vv.w, o[d + 3]);
            }
        }
    }

    // Normalize + direct coalesced-enough write into [L, DMODEL] layout
    const float inv = 1.0f / lsum;
    float* op = g_attn + (size_t)i * DMODEL + h * HDIM + hf * 32;
#pragma unroll
    for (int d = 0; d < 32; d += 4) {
        float4 v = make_float4(o[d] * inv, o[d + 1] * inv, o[d + 2] * inv, o[d + 3] * inv);
        *(float4*)&op[d] = v;
    }
}

// ---------------------------------------------------------------------------
extern "C" void kernel_launch(void* const* d_in, const int* in_sizes, int n_in,
                              void* d_out, int out_size) {
    const float* x  = (const float*)d_in[0];
    const float* qw = (const float*)d_in[1];
    const float* kw = (const float*)d_in[2];
    const float* vw = (const float*)d_in[3];
    const float* ow = (const float*)d_in[4];
    float* out = (float*)d_out;

    float *pq, *pk, *pv, *pa;
    cudaGetSymbolAddress((void**)&pq, g_q);
    cudaGetSymbolAddress((void**)&pk, g_k);
    cudaGetSymbolAddress((void**)&pv, g_v);
    cudaGetSymbolAddress((void**)&pa, g_attn);

    dim3 gp(DMODEL / BN, L_SEQ / BM);
    sgemm<1><<<gp, 256>>>(x, qw, pq, L_SEQ, DMODEL, DMODEL);
    sgemm<1><<<gp, 256>>>(x, kw, pk, L_SEQ, DMODEL, DMODEL);
    sgemm<1><<<gp, 256>>>(x, vw, pv, L_SEQ, DMODEL, DMODEL);

    dim3 ga(L_SEQ / 64, NHEADS);
    attn_kernel<<<ga, 128>>>();

    sgemm<0><<<gp, 256>>>(pa, ow, out, L_SEQ, DMODEL, DMODEL);
}

// round 3
// speedup vs baseline: 1.7290x; 1.4001x over previous
#include <cuda_runtime.h>
#include <math.h>

#define L_SEQ  4096
#define DMODEL 1024
#define NHEADS 16
#define HDIM   64

typedef unsigned long long ull;

// Scratch (allocation-free rule: __device__ globals)
__device__ float g_q[NHEADS * L_SEQ * HDIM];
__device__ float g_k[NHEADS * L_SEQ * HDIM];
__device__ float g_v[NHEADS * L_SEQ * HDIM];
__device__ float g_attn[L_SEQ * DMODEL];

// ---- packed fp32x2 helpers (Blackwell FFMA2 path) ----
__device__ __forceinline__ ull pk2(float x, float y) {
    ull r; asm("mov.b64 %0, {%1, %2};" : "=l"(r) : "f"(x), "f"(y)); return r;
}
__device__ __forceinline__ float2 upk2(ull v) {
    float2 r; asm("mov.b64 {%0, %1}, %2;" : "=f"(r.x), "=f"(r.y) : "l"(v)); return r;
}
__device__ __forceinline__ ull ffma2(ull a, ull b, ull c) {
    ull d; asm("fma.rn.f32x2 %0, %1, %2, %3;" : "=l"(d) : "l"(a), "l"(b), "l"(c)); return d;
}
__device__ __forceinline__ ull fmul2(ull a, ull b) {
    ull d; asm("mul.rn.f32x2 %0, %1, %2;" : "=l"(d) : "l"(a), "l"(b)); return d;
}

union F4U2 { float4 f; ull u[2]; };

// ---------------------------------------------------------------------------
// SGEMM: C = A(MxK) * B(KxN), row-major fp32. 128x128x16 tile, 256 threads,
// 8x8 per thread via FFMA2 (32 packed FMA per k-step), reg double-buffered.
// MODE 0: C[row*N + col]
// MODE 1: head-major: C[((col>>6)*M + row)*64 + (col&63)]
// ---------------------------------------------------------------------------
#define BM 128
#define BN 128
#define BK 16

template <int MODE>
__global__ __launch_bounds__(256, 2) void sgemm(const float* __restrict__ A,
                                                const float* __restrict__ B,
                                                float* __restrict__ C,
                                                int M, int N, int K) {
    __shared__ float As[BK * 132];  // [k][m], padded
    __shared__ float Bs[BK * BN];   // [k][n]

    const int tid  = threadIdx.x;
    const int tx   = tid & 15;
    const int ty   = tid >> 4;
    const int row0 = blockIdx.y * BM;
    const int col0 = blockIdx.x * BN;

    const int a_row0 = tid >> 2;
    const int a_kq   = tid & 3;
    const int b_k0 = tid >> 5;
    const int b_n4 = tid & 31;

    ull acc2[8][4];
#pragma unroll
    for (int i = 0; i < 8; i++)
#pragma unroll
        for (int j = 0; j < 4; j++) acc2[i][j] = 0ull;

    float4 a_ld[2], b_ld[2];

#pragma unroll
    for (int i = 0; i < 2; i++) {
        a_ld[i] = *(const float4*)&A[(size_t)(row0 + a_row0 + i * 64) * K + a_kq * 4];
        b_ld[i] = *(const float4*)&B[(size_t)(b_k0 + i * 8) * N + col0 + b_n4 * 4];
    }
#pragma unroll
    for (int i = 0; i < 2; i++) {
        int r = a_row0 + i * 64;
        As[(a_kq * 4 + 0) * 132 + r] = a_ld[i].x;
        As[(a_kq * 4 + 1) * 132 + r] = a_ld[i].y;
        As[(a_kq * 4 + 2) * 132 + r] = a_ld[i].z;
        As[(a_kq * 4 + 3) * 132 + r] = a_ld[i].w;
        *(float4*)&Bs[(b_k0 + i * 8) * BN + b_n4 * 4] = b_ld[i];
    }
    __syncthreads();

    for (int k0 = 0; k0 < K; k0 += BK) {
        const bool has_next = (k0 + BK) < K;
        if (has_next) {
#pragma unroll
            for (int i = 0; i < 2; i++) {
                a_ld[i] = *(const float4*)&A[(size_t)(row0 + a_row0 + i * 64) * K + k0 + BK + a_kq * 4];
                b_ld[i] = *(const float4*)&B[(size_t)(k0 + BK + b_k0 + i * 8) * N + col0 + b_n4 * 4];
            }
        }

#pragma unroll
        for (int k = 0; k < BK; k++) {
            float a[8];
            F4U2 bb0, bb1;
            *(float4*)&a[0] = *(float4*)&As[k * 132 + ty * 4];
            *(float4*)&a[4] = *(float4*)&As[k * 132 + 64 + ty * 4];
            bb0.f = *(float4*)&Bs[k * BN + tx * 4];
            bb1.f = *(float4*)&Bs[k * BN + 64 + tx * 4];
            ull b2[4] = {bb0.u[0], bb0.u[1], bb1.u[0], bb1.u[1]};
#pragma unroll
            for (int i = 0; i < 8; i++) {
                ull A2 = pk2(a[i], a[i]);
#pragma unroll
                for (int j = 0; j < 4; j++)
                    acc2[i][j] = ffma2(A2, b2[j], acc2[i][j]);
            }
        }
        __syncthreads();
        if (has_next) {
#pragma unroll
            for (int i = 0; i < 2; i++) {
                int r = a_row0 + i * 64;
                As[(a_kq * 4 + 0) * 132 + r] = a_ld[i].x;
                As[(a_kq * 4 + 1) * 132 + r] = a_ld[i].y;
                As[(a_kq * 4 + 2) * 132 + r] = a_ld[i].z;
                As[(a_kq * 4 + 3) * 132 + r] = a_ld[i].w;
                *(float4*)&Bs[(b_k0 + i * 8) * BN + b_n4 * 4] = b_ld[i];
            }
            __syncthreads();
        }
    }

    // Epilogue: unpack pairs -> cols {tx*4+0..3} and {64+tx*4+0..3}
#pragma unroll
    for (int ci = 0; ci < 2; ci++) {
#pragma unroll
        for (int r = 0; r < 4; r++) {
            int row = row0 + ci * 64 + ty * 4 + r;
#pragma unroll
            for (int cj = 0; cj < 2; cj++) {
                float2 lo = upk2(acc2[ci * 4 + r][cj * 2 + 0]);
                float2 hi = upk2(acc2[ci * 4 + r][cj * 2 + 1]);
                int col = col0 + cj * 64 + tx * 4;
                float4 v = make_float4(lo.x, lo.y, hi.x, hi.y);
                if (MODE == 0) {
                    *(float4*)&C[(size_t)row * N + col] = v;
                } else {
                    int head = col >> 6;
                    *(float4*)&C[((size_t)head * M + row) * 64 + (col & 63)] = v;
                }
            }
        }
    }
}

// ---------------------------------------------------------------------------
// Flash attention, register-tiled + FFMA2.
// Block = (head, 64 q-rows), 128 threads: tx = t&7 (8 key/d-col groups),
// ty = t>>3 (16 row groups of 4). Per tile:
//   QK^T: S frag 4x8 per thread, k-dim = d (Qt,Kt transposed in smem)
//   softmax in regs (shfl over tx-siblings)
//   P staged transposed [key][row] in the Kt buffer
//   PV:   O frag 4x8 per thread, k-dim = key
// ---------------------------------------------------------------------------
__global__ __launch_bounds__(128, 3) void attn_kernel() {
    __shared__ float Qt[64 * 64];    // [d][row], prescaled by 0.125
    __shared__ float KtPt[64 * 64];  // QK: Kt [d][key]; PV: Pt [key][row]
    __shared__ float Vs[64 * 64];    // [key][d]

    const int h  = blockIdx.y;
    const int bx = (int)gridDim.x - 1 - (int)blockIdx.x;  // big tiles first
    const int i0 = bx * 64;
    const int t  = threadIdx.x;
    const int tx = t & 7;
    const int ty = t >> 3;
    const int r0 = ty * 4;
    const float slope = exp2f(-0.5f * (float)(h + 1));

    // Q transpose load (lanes span 32 distinct rows -> conflict-free STS)
    {
        const float* qp = g_q + ((size_t)h * L_SEQ + i0) * HDIM;
#pragma unroll
        for (int idx = t; idx < 1024; idx += 128) {
            int row = idx & 63, dg = idx >> 6;
            float4 v = *(const float4*)&qp[row * 64 + dg * 4];
            Qt[(dg * 4 + 0) * 64 + row] = v.x * 0.125f;
            Qt[(dg * 4 + 1) * 64 + row] = v.y * 0.125f;
            Qt[(dg * 4 + 2) * 64 + row] = v.z * 0.125f;
            Qt[(dg * 4 + 3) * 64 + row] = v.w * 0.125f;
        }
    }

    float m[4], l[4];
    ull o2[4][4];
#pragma unroll
    for (int r = 0; r < 4; r++) {
        m[r] = -INFINITY; l[r] = 0.f;
#pragma unroll
        for (int c = 0; c < 4; c++) o2[r][c] = 0ull;
    }

    for (int kb = 0; kb <= bx; kb++) {
        const int j0 = kb * 64;
        const float* kp = g_k + ((size_t)h * L_SEQ + j0) * HDIM;
        const float* vp = g_v + ((size_t)h * L_SEQ + j0) * HDIM;
        __syncthreads();  // prev PV reads of KtPt/Vs done (also Qt ready, iter 0)
#pragma unroll
        for (int idx = t; idx < 1024; idx += 128) {
            int key = idx & 63, dg = idx >> 6;
            float4 v = *(const float4*)&kp[key * 64 + dg * 4];
            KtPt[(dg * 4 + 0) * 64 + key] = v.x;
            KtPt[(dg * 4 + 1) * 64 + key] = v.y;
            KtPt[(dg * 4 + 2) * 64 + key] = v.z;
            KtPt[(dg * 4 + 3) * 64 + key] = v.w;
        }
#pragma unroll
        for (int idx = t; idx < 1024; idx += 128)
            *(float4*)&Vs[idx * 4] = *(const float4*)&vp[idx * 4];
        __syncthreads();

        // ---- QK^T: s2[4 rows][4 key-pairs], k-dim = d ----
        ull s2[4][4];
#pragma unroll
        for (int r = 0; r < 4; r++)
#pragma unroll
            for (int c = 0; c < 4; c++) s2[r][c] = 0ull;

#pragma unroll 8
        for (int d = 0; d < 64; d++) {
            float4 a = *(const float4*)&Qt[d * 64 + r0];
            F4U2 bb0, bb1;
            bb0.f = *(const float4*)&KtPt[d * 64 + tx * 8];
            bb1.f = *(const float4*)&KtPt[d * 64 + tx * 8 + 4];
            ull b2[4] = {bb0.u[0], bb0.u[1], bb1.u[0], bb1.u[1]};
            float av[4] = {a.x, a.y, a.z, a.w};
#pragma unroll
            for (int r = 0; r < 4; r++) {
                ull A2 = pk2(av[r], av[r]);
#pragma unroll
                for (int c = 0; c < 4; c++)
                    s2[r][c] = ffma2(A2, b2[c], s2[r][c]);
            }
        }

        // ---- softmax (ALiBi + causal) ----
        float s[4][8];
        const bool diag = (kb == bx);
#pragma unroll
        for (int r = 0; r < 4; r++) {
            int ig = i0 + r0 + r;
#pragma unroll
            for (int c = 0; c < 4; c++) {
                float2 f = upk2(s2[r][c]);
                int jg = j0 + tx * 8 + 2 * c;
                s[r][2 * c + 0] = f.x - slope * (float)(ig - jg);
                s[r][2 * c + 1] = f.y - slope * (float)(ig - jg - 1);
                if (diag) {
                    if (jg > ig)     s[r][2 * c + 0] = -INFINITY;
                    if (jg + 1 > ig) s[r][2 * c + 1] = -INFINITY;
                }
            }
        }

        float mt[4];
#pragma unroll
        for (int r = 0; r < 4; r++) {
            float v = s[r][0];
#pragma unroll
            for (int k = 1; k < 8; k++) v = fmaxf(v, s[r][k]);
            v = fmaxf(v, __shfl_xor_sync(0xffffffffu, v, 1));
            v = fmaxf(v, __shfl_xor_sync(0xffffffffu, v, 2));
            v = fmaxf(v, __shfl_xor_sync(0xffffffffu, v, 4));
            mt[r] = fmaxf(m[r], v);
        }
#pragma unroll
        for (int r = 0; r < 4; r++) {
            float corr = __expf(m[r] - mt[r]);  // -inf start -> 0
            m[r] = mt[r];
            l[r] *= corr;
            ull c2 = pk2(corr, corr);
#pragma unroll
            for (int c = 0; c < 4; c++) o2[r][c] = fmul2(o2[r][c], c2);
#pragma unroll
            for (int k = 0; k < 8; k++) {
                float p = __expf(s[r][k] - m[r]);
                s[r][k] = p;
                l[r] += p;
            }
        }

        __syncthreads();  // all QK reads of Kt done
#pragma unroll
        for (int kk = 0; kk < 8; kk++) {
            int key = tx * 8 + kk;
            *(float4*)&KtPt[key * 64 + r0] =
                make_float4(s[0][kk], s[1][kk], s[2][kk], s[3][kk]);
        }
        __syncthreads();

        // ---- PV: o2[4 rows][4 d-pairs], k-dim = key ----
#pragma unroll 8
        for (int key = 0; key < 64; key++) {
            float4 a = *(const float4*)&KtPt[key * 64 + r0];
            F4U2 vv0, vv1;
            vv0.f = *(const float4*)&Vs[key * 64 + tx * 8];
            vv1.f = *(const float4*)&Vs[key * 64 + tx * 8 + 4];
            ull v2[4] = {vv0.u[0], vv0.u[1], vv1.u[0], vv1.u[1]};
            float av[4] = {a.x, a.y, a.z, a.w};
#pragma unroll
            for (int r = 0; r < 4; r++) {
                ull A2 = pk2(av[r], av[r]);
#pragma unroll
                for (int c = 0; c < 4; c++)
                    o2[r][c] = ffma2(A2, v2[c], o2[r][c]);
            }
        }
    }

    // Final: reduce l over tx-siblings, normalize, store
#pragma unroll
    for (int r = 0; r < 4; r++) {
        float lv = l[r];
        lv += __shfl_xor_sync(0xffffffffu, lv, 1);
        lv += __shfl_xor_sync(0xffffffffu, lv, 2);
        lv += __shfl_xor_sync(0xffffffffu, lv, 4);
        float inv = 1.0f / lv;
        float* op = g_attn + (size_t)(i0 + r0 + r) * DMODEL + h * HDIM + tx * 8;
        float2 p0 = upk2(o2[r][0]), p1 = upk2(o2[r][1]);
        float2 p2 = upk2(o2[r][2]), p3 = upk2(o2[r][3]);
        *(float4*)&op[0] = make_float4(p0.x * inv, p0.y * inv, p1.x * inv, p1.y * inv);
        *(float4*)&op[4] = make_float4(p2.x * inv, p2.y * inv, p3.x * inv, p3.y * inv);
    }
}

// ---------------------------------------------------------------------------
extern "C" void kernel_launch(void* const* d_in, const int* in_sizes, int n_in,
                              void* d_out, int out_size) {
    const float* x  = (const float*)d_in[0];
    const float* qw = (const float*)d_in[1];
    const float* kw = (const float*)d_in[2];
    const float* vw = (const float*)d_in[3];
    const float* ow = (const float*)d_in[4];
    float* out = (float*)d_out;

    float *pq, *pk, *pv, *pa;
    cudaGetSymbolAddress((void**)&pq, g_q);
    cudaGetSymbolAddress((void**)&pk, g_k);
    cudaGetSymbolAddress((void**)&pv, g_v);
    cudaGetSymbolAddress((void**)&pa, g_attn);

    dim3 gp(DMODEL / BN, L_SEQ / BM);
    sgemm<1><<<gp, 256>>>(x, qw, pq, L_SEQ, DMODEL, DMODEL);
    sgemm<1><<<gp, 256>>>(x, kw, pk, L_SEQ, DMODEL, DMODEL);
    sgemm<1><<<gp, 256>>>(x, vw, pv, L_SEQ, DMODEL, DMODEL);

    dim3 ga(L_SEQ / 64, NHEADS);
    attn_kernel<<<ga, 128>>>();

    sgemm<0><<<gp, 256>>>(pa, ow, out, L_SEQ, DMODEL, DMODEL);
}